// round 2
// baseline (speedup 1.0000x reference)
#include <cuda_runtime.h>

#define BB 4096
#define TT 200
#define DD 128
#define KS 5
#define NTHREADS 256

// smem layout (float offsets)
#define OFF_ITEMS 0          // 25600
#define OFF_MASK  25600      // 200
#define OFF_AGE   25800      // 200
#define OFF_POP   26000      // 200
#define OFF_SC    26200      // 200
#define OFF_MEAN  26400      // 128
#define OFF_R     26528      // 128
#define OFF_W     26656      // 256
#define OFF_LT    26912      // 128
#define OFF_PART  27040      // 1024
#define OFF_RED   28064      // 8
#define OFF_SCAL  28072      // 4
#define SMEM_FLOATS 28080
#define SMEM_BYTES (SMEM_FLOATS * 4)

// A = Wq^T Wk, A[d*DD+e] = sum_i Wq[i*DD+d] * Wk[i*DD+e]
__device__ float g_A[DD * DD];

__global__ void compute_A_kernel(const float* __restrict__ Wq,
                                 const float* __restrict__ Wk) {
    int d = blockIdx.x;
    int e = threadIdx.x;
    float s = 0.f;
#pragma unroll 8
    for (int i = 0; i < DD; ++i)
        s += Wq[i * DD + d] * Wk[i * DD + e];
    g_A[d * DD + e] = s;
}

__device__ __forceinline__ float warp_sum(float v) {
#pragma unroll
    for (int o = 16; o; o >>= 1) v += __shfl_xor_sync(0xffffffffu, v, o);
    return v;
}
__device__ __forceinline__ float warp_max(float v) {
#pragma unroll
    for (int o = 16; o; o >>= 1) v = fmaxf(v, __shfl_xor_sync(0xffffffffu, v, o));
    return v;
}

__global__ void __launch_bounds__(NTHREADS, 1)
user_enc_kernel(const float* __restrict__ items_g,
                const int* __restrict__ mask_g,
                const float* __restrict__ age_g,
                const float* __restrict__ pop_g,
                const float* __restrict__ Wv,
                const float* __restrict__ gate_w,
                const float* __restrict__ gate_b,
                const float* __restrict__ ln_g,
                const float* __restrict__ ln_b,
                const float* __restrict__ dalpha,
                float* __restrict__ out) {
    extern __shared__ float sm[];
    float* s_items = sm + OFF_ITEMS;
    float* s_mask  = sm + OFF_MASK;
    float* s_age   = sm + OFF_AGE;
    float* s_pop   = sm + OFF_POP;
    float* s_sc    = sm + OFF_SC;
    float* s_mean  = sm + OFF_MEAN;
    float* s_r     = sm + OFF_R;
    float* s_w     = sm + OFF_W;
    float* s_lt    = sm + OFF_LT;
    float* s_part  = sm + OFF_PART;
    float* s_red   = sm + OFF_RED;
    float* s_scal  = sm + OFF_SCAL;

    const int tid  = threadIdx.x;
    const int lane = tid & 31;
    const int warp = tid >> 5;
    const int b    = blockIdx.x;
    const float NEG_INF = __int_as_float(0xff800000);

    // ---- phase 0: row metadata ----
    if (tid < TT) {
        s_mask[tid] = (mask_g[(size_t)b * TT + tid] != 0) ? 1.f : 0.f;
        s_age[tid]  = age_g[(size_t)b * TT + tid];
        s_pop[tid]  = pop_g[(size_t)b * TT + tid];
    }
    __syncthreads();

    // ---- phase 1: load items row into smem, fused masked partial sums ----
    const float4* g4 = (const float4*)(items_g + (size_t)b * TT * DD);
    float4* s4 = (float4*)s_items;
    float4 acc = make_float4(0.f, 0.f, 0.f, 0.f);
#pragma unroll 5
    for (int k = 0; k < (TT * DD / 4) / NTHREADS; ++k) {  // 25 iters
        int i = tid + k * NTHREADS;
        float4 v = g4[i];
        s4[i] = v;
        float m = s_mask[i >> 5];  // 32 float4 per row -> t = i/32
        acc.x += m * v.x; acc.y += m * v.y; acc.z += m * v.z; acc.w += m * v.w;
    }
    ((float4*)s_part)[tid] = acc;

    // cnt = sum(mask) by warp 0
    if (warp == 0) {
        float c = 0.f;
        for (int t = lane; t < TT; t += 32) c += s_mask[t];
        c = warp_sum(c);
        if (lane == 0) s_scal[0] = c;
    }
    __syncthreads();

    const float cntf = s_scal[0];

    // ---- masked mean ----
    if (tid < DD) {
        int d4 = tid >> 2, comp = tid & 3;
        float s = 0.f;
#pragma unroll
        for (int j = 0; j < 8; ++j)
            s += s_part[(j * 32 + d4) * 4 + comp];
        s_mean[tid] = s / (cntf + 1e-6f);
    }
    __syncthreads();

    // ---- r[e] = sum_d mean[d] * A[d,e]  (A in L2, coalesced) ----
    if (tid < DD) {
        float r = 0.f;
#pragma unroll 8
        for (int d = 0; d < DD; ++d)
            r += s_mean[d] * g_A[d * DD + tid];
        s_r[tid] = r;
    }
    __syncthreads();

    // ---- scores: warp-per-t dot(r, x_t) ----
    const float alpha = log1pf(expf(dalpha[0])) + 1e-6f;
    const float scale = 0.08838834764831845f;  // 1/sqrt(128)
    {
        float4 rv = ((const float4*)s_r)[lane];
        for (int t = warp; t < TT; t += 8) {
            float4 xv = s4[t * 32 + lane];
            float dot = xv.x * rv.x + xv.y * rv.y + xv.z * rv.z + xv.w * rv.w;
            dot = warp_sum(dot);
            if (lane == 0) {
                float sc;
                if (s_mask[t] != 0.f)
                    sc = dot * scale + logf(expf(-alpha * s_age[t]) + 1e-12f);
                else
                    sc = NEG_INF;
                s_sc[t] = sc;
            }
        }
    }
    __syncthreads();

    // ---- softmax over T ----
    {
        float lm = (tid < TT) ? s_sc[tid] : NEG_INF;
        lm = warp_max(lm);
        if (lane == 0) s_red[warp] = lm;
        __syncthreads();
        if (tid == 0) {
            float m = s_red[0];
#pragma unroll
            for (int j = 1; j < 8; ++j) m = fmaxf(m, s_red[j]);
            s_scal[1] = m;
        }
        __syncthreads();
        float smax = s_scal[1];
        float p = (tid < TT) ? expf(s_sc[tid] - smax) : 0.f;
        if (tid < TT) s_sc[tid] = p;
        float ls = warp_sum(p);
        if (lane == 0) s_red[warp] = ls;
        __syncthreads();
        if (tid == 0) {
            float s = 0.f;
#pragma unroll
            for (int j = 0; j < 8; ++j) s += s_red[j];
            s_scal[2] = s;
        }
        __syncthreads();
    }
    const float inv = 1.f / s_scal[2];

    // ---- weighted sum w[d] = (1/Z) sum_t p_t x[t,d], split over 2 halves ----
    {
        int d = tid & 127, half = tid >> 7;
        float w = 0.f;
        int t0 = half * 100;
#pragma unroll 4
        for (int t = t0; t < t0 + 100; ++t)
            w += s_sc[t] * s_items[t * DD + d];
        s_w[half * DD + d] = w;
    }
    __syncthreads();
    if (tid < DD)
        s_w[tid] = (s_w[tid] + s_w[DD + tid]) * inv;
    __syncthreads();

    // ---- long_term[e] = sum_d Wv[e,d] w[d]  (warp-per-e, coalesced L2) ----
    {
        float4 wv4 = ((const float4*)s_w)[lane];
        for (int e = warp; e < DD; e += 8) {
            float4 m4 = ((const float4*)(Wv + e * DD))[lane];
            float dot = m4.x * wv4.x + m4.y * wv4.y + m4.z * wv4.z + m4.w * wv4.w;
            dot = warp_sum(dot);
            if (lane == 0) s_lt[e] = dot;
        }
    }
    __syncthreads();

    // ---- short-term window, gate, combine, LayerNorm ----
    float u = 0.f;
    if (tid < DD) {
        int cnt = (int)(cntf + 0.5f);
        if (cnt < 1) cnt = 1;
        int start = cnt - KS;
        if (start < 0) start = 0;
        float dn = (float)(cnt - start);

        float st = 0.f;
        for (int t = start; t < cnt; ++t) st += s_items[t * DD + tid];
        st /= dn;

        float mp = 0.f, mr = 0.f;
        for (int t = start; t < cnt; ++t) { mp += s_pop[t]; mr += s_age[t]; }
        mp /= dn; mr /= dn;

        float z = mp * gate_w[0] + mr * gate_w[1] + gate_b[0];
        float g = 1.f / (1.f + expf(-z));
        u = g * st + (1.f - g) * s_lt[tid];
    }

    // block LN over 128 values (warps 0-3 hold them)
    {
        float v1 = (tid < DD) ? u : 0.f;
        v1 = warp_sum(v1);
        if (lane == 0) s_red[warp] = v1;
        __syncthreads();
        float mu = (s_red[0] + s_red[1] + s_red[2] + s_red[3]) * (1.f / 128.f);
        __syncthreads();
        float d2 = (tid < DD) ? (u - mu) * (u - mu) : 0.f;
        d2 = warp_sum(d2);
        if (lane == 0) s_red[warp] = d2;
        __syncthreads();
        float var = (s_red[0] + s_red[1] + s_red[2] + s_red[3]) * (1.f / 128.f);
        if (tid < DD) {
            float o = (u - mu) * rsqrtf(var + 1e-5f) * ln_g[tid] + ln_b[tid];
            out[(size_t)b * DD + tid] = o;
        }
    }
}

extern "C" void kernel_launch(void* const* d_in, const int* in_sizes, int n_in,
                              void* d_out, int out_size) {
    const float* items = (const float*)d_in[0];
    const int*   mask  = (const int*)d_in[1];
    const float* age   = (const float*)d_in[2];
    const float* pop   = (const float*)d_in[3];
    const float* Wq    = (const float*)d_in[4];
    const float* Wk    = (const float*)d_in[5];
    const float* Wv    = (const float*)d_in[6];
    const float* gw    = (const float*)d_in[7];
    const float* gb    = (const float*)d_in[8];
    const float* lng   = (const float*)d_in[9];
    const float* lnb   = (const float*)d_in[10];
    const float* da    = (const float*)d_in[11];
    float* out = (float*)d_out;

    compute_A_kernel<<<DD, DD>>>(Wq, Wk);

    cudaFuncSetAttribute(user_enc_kernel,
                         cudaFuncAttributeMaxDynamicSharedMemorySize, SMEM_BYTES);
    user_enc_kernel<<<BB, NTHREADS, SMEM_BYTES>>>(items, mask, age, pop, Wv,
                                                  gw, gb, lng, lnb, da, out);
}

// round 3
// speedup vs baseline: 1.3702x; 1.3702x over previous
#include <cuda_runtime.h>

#define BB 4096
#define TT 200
#define DD 128
#define KS 5
#define NTHREADS 256

// smem layout (float offsets)
#define OFF_ITEMS 0          // 25600
#define OFF_MASK  25600      // 200
#define OFF_AGE   25800      // 200
#define OFF_POP   26000      // 200
#define OFF_SC    26200      // 200
#define OFF_DLOG  26400      // 200
#define OFF_MEAN  26600      // 128
#define OFF_R     26728      // 128
#define OFF_W     26856      // 256
#define OFF_LT    27112      // 128
#define OFF_PART  27240      // 1024
#define OFF_RED   28264      // 8
#define OFF_SCAL  28272      // 4
#define SMEM_FLOATS 28280
#define SMEM_BYTES (SMEM_FLOATS * 4)

// A = Wq^T Wk, A[d*DD+e] = sum_i Wq[i*DD+d] * Wk[i*DD+e]
__device__ float g_A[DD * DD];

__global__ void compute_A_kernel(const float* __restrict__ Wq,
                                 const float* __restrict__ Wk) {
    int d = blockIdx.x;
    int e = threadIdx.x;
    float s = 0.f;
#pragma unroll 16
    for (int i = 0; i < DD; ++i)
        s += Wq[i * DD + d] * Wk[i * DD + e];
    g_A[d * DD + e] = s;
}

__device__ __forceinline__ float warp_sum(float v) {
#pragma unroll
    for (int o = 16; o; o >>= 1) v += __shfl_xor_sync(0xffffffffu, v, o);
    return v;
}
__device__ __forceinline__ float warp_max(float v) {
#pragma unroll
    for (int o = 16; o; o >>= 1) v = fmaxf(v, __shfl_xor_sync(0xffffffffu, v, o));
    return v;
}

__global__ void __launch_bounds__(NTHREADS, 1)
user_enc_kernel(const float* __restrict__ items_g,
                const int* __restrict__ mask_g,
                const float* __restrict__ age_g,
                const float* __restrict__ pop_g,
                const float* __restrict__ Wv,
                const float* __restrict__ gate_w,
                const float* __restrict__ gate_b,
                const float* __restrict__ ln_g,
                const float* __restrict__ ln_b,
                const float* __restrict__ dalpha,
                float* __restrict__ out) {
    extern __shared__ float sm[];
    float* s_items = sm + OFF_ITEMS;
    float* s_mask  = sm + OFF_MASK;
    float* s_age   = sm + OFF_AGE;
    float* s_pop   = sm + OFF_POP;
    float* s_sc    = sm + OFF_SC;
    float* s_dlog  = sm + OFF_DLOG;
    float* s_mean  = sm + OFF_MEAN;
    float* s_r     = sm + OFF_R;
    float* s_w     = sm + OFF_W;
    float* s_lt    = sm + OFF_LT;
    float* s_part  = sm + OFF_PART;
    float* s_red   = sm + OFF_RED;
    float* s_scal  = sm + OFF_SCAL;

    const int tid  = threadIdx.x;
    const int lane = tid & 31;
    const int warp = tid >> 5;
    const int b    = blockIdx.x;
    const float NEG_INF = __int_as_float(0xff800000);

    // ---- phase 0: row metadata + parallel decay-log precompute ----
    const float alpha = log1pf(expf(dalpha[0])) + 1e-6f;
    if (tid < TT) {
        int m = mask_g[(size_t)b * TT + tid];
        float a = age_g[(size_t)b * TT + tid];
        s_mask[tid] = m ? 1.f : 0.f;
        s_age[tid]  = a;
        s_pop[tid]  = pop_g[(size_t)b * TT + tid];
        // log(exp(-alpha*age) + 1e-12), or -inf when masked off
        s_dlog[tid] = m ? __logf(__expf(-alpha * a) + 1e-12f) : NEG_INF;
    }
    __syncthreads();

    // ---- phase 1: load items row into smem, fused masked partial sums ----
    const float4* g4 = (const float4*)(items_g + (size_t)b * TT * DD);
    float4* s4 = (float4*)s_items;
    float4 acc = make_float4(0.f, 0.f, 0.f, 0.f);
#pragma unroll 5
    for (int k = 0; k < (TT * DD / 4) / NTHREADS; ++k) {  // 25 iters
        int i = tid + k * NTHREADS;
        float4 v = g4[i];
        s4[i] = v;
        float m = s_mask[i >> 5];  // 32 float4 per row -> t = i/32
        acc.x += m * v.x; acc.y += m * v.y; acc.z += m * v.z; acc.w += m * v.w;
    }
    ((float4*)s_part)[tid] = acc;

    // cnt = sum(mask) by warp 0
    if (warp == 0) {
        float c = 0.f;
        for (int t = lane; t < TT; t += 32) c += s_mask[t];
        c = warp_sum(c);
        if (lane == 0) s_scal[0] = c;
    }
    __syncthreads();

    const float cntf = s_scal[0];

    // ---- masked mean ----
    if (tid < DD) {
        int d4 = tid >> 2, comp = tid & 3;
        float s = 0.f;
#pragma unroll
        for (int j = 0; j < 8; ++j)
            s += s_part[(j * 32 + d4) * 4 + comp];
        s_mean[tid] = s / (cntf + 1e-6f);
    }
    __syncthreads();

    // ---- r[e] = sum_d mean[d] * A[d,e], split d over 2 thread halves ----
    {
        int e = tid & 127, half = tid >> 7;
        const float* Ap = g_A + (size_t)half * 64 * DD + e;
        const float* mp = s_mean + half * 64;
        float r = 0.f;
#pragma unroll 16
        for (int d = 0; d < 64; ++d)
            r += mp[d] * Ap[(size_t)d * DD];
        s_part[half * DD + e] = r;
    }
    __syncthreads();
    if (tid < DD) s_r[tid] = s_part[tid] + s_part[DD + tid];
    __syncthreads();

    // ---- scores: warp-per-t dot(r, x_t), pipelined ----
    const float scale = 0.08838834764831845f;  // 1/sqrt(128)
    {
        float4 rv = ((const float4*)s_r)[lane];
#pragma unroll 5
        for (int t = warp; t < TT; t += 8) {
            float4 xv = s4[t * 32 + lane];
            float dot = xv.x * rv.x + xv.y * rv.y + xv.z * rv.z + xv.w * rv.w;
            dot = warp_sum(dot);
            if (lane == 0) {
                float dl = s_dlog[t];
                s_sc[t] = (dl == NEG_INF) ? NEG_INF : dot * scale + dl;
            }
        }
    }
    __syncthreads();

    // ---- softmax over T ----
    {
        float lm = (tid < TT) ? s_sc[tid] : NEG_INF;
        lm = warp_max(lm);
        if (lane == 0) s_red[warp] = lm;
        __syncthreads();
        if (tid == 0) {
            float m = s_red[0];
#pragma unroll
            for (int j = 1; j < 8; ++j) m = fmaxf(m, s_red[j]);
            s_scal[1] = m;
        }
        __syncthreads();
        float smax = s_scal[1];
        float p = (tid < TT) ? __expf(s_sc[tid] - smax) : 0.f;
        if (tid < TT) s_sc[tid] = p;
        float ls = warp_sum(p);
        if (lane == 0) s_red[warp] = ls;
        __syncthreads();
        if (tid == 0) {
            float s = 0.f;
#pragma unroll
            for (int j = 0; j < 8; ++j) s += s_red[j];
            s_scal[2] = s;
        }
        __syncthreads();
    }
    const float inv = 1.f / s_scal[2];

    // ---- weighted sum w[d] = (1/Z) sum_t p_t x[t,d], split over 2 halves ----
    {
        int d = tid & 127, half = tid >> 7;
        float w = 0.f;
        int t0 = half * 100;
#pragma unroll 10
        for (int t = t0; t < t0 + 100; ++t)
            w += s_sc[t] * s_items[t * DD + d];
        s_w[half * DD + d] = w;
    }
    __syncthreads();
    if (tid < DD)
        s_w[tid] = (s_w[tid] + s_w[DD + tid]) * inv;
    __syncthreads();

    // ---- long_term[e] = sum_d Wv[e,d] w[d]  (warp-per-e, coalesced L2) ----
    {
        float4 wv4 = ((const float4*)s_w)[lane];
#pragma unroll 4
        for (int e = warp; e < DD; e += 8) {
            float4 m4 = ((const float4*)(Wv + (size_t)e * DD))[lane];
            float dot = m4.x * wv4.x + m4.y * wv4.y + m4.z * wv4.z + m4.w * wv4.w;
            dot = warp_sum(dot);
            if (lane == 0) s_lt[e] = dot;
        }
    }
    __syncthreads();

    // ---- short-term window, gate, combine, LayerNorm ----
    float u = 0.f;
    if (tid < DD) {
        int cnt = (int)(cntf + 0.5f);
        if (cnt < 1) cnt = 1;
        int start = cnt - KS;
        if (start < 0) start = 0;
        float dn = (float)(cnt - start);

        float st = 0.f;
        for (int t = start; t < cnt; ++t) st += s_items[t * DD + tid];
        st /= dn;

        float mp = 0.f, mr = 0.f;
        for (int t = start; t < cnt; ++t) { mp += s_pop[t]; mr += s_age[t]; }
        mp /= dn; mr /= dn;

        float z = mp * gate_w[0] + mr * gate_w[1] + gate_b[0];
        float g = 1.f / (1.f + __expf(-z));
        u = g * st + (1.f - g) * s_lt[tid];
    }

    // block LN over 128 values (warps 0-3 hold them)
    {
        float v1 = (tid < DD) ? u : 0.f;
        v1 = warp_sum(v1);
        if (lane == 0) s_red[warp] = v1;
        __syncthreads();
        float mu = (s_red[0] + s_red[1] + s_red[2] + s_red[3]) * (1.f / 128.f);
        __syncthreads();
        float d2 = (tid < DD) ? (u - mu) * (u - mu) : 0.f;
        d2 = warp_sum(d2);
        if (lane == 0) s_red[warp] = d2;
        __syncthreads();
        float var = (s_red[0] + s_red[1] + s_red[2] + s_red[3]) * (1.f / 128.f);
        if (tid < DD) {
            float o = (u - mu) * rsqrtf(var + 1e-5f) * ln_g[tid] + ln_b[tid];
            out[(size_t)b * DD + tid] = o;
        }
    }
}

extern "C" void kernel_launch(void* const* d_in, const int* in_sizes, int n_in,
                              void* d_out, int out_size) {
    const float* items = (const float*)d_in[0];
    const int*   mask  = (const int*)d_in[1];
    const float* age   = (const float*)d_in[2];
    const float* pop   = (const float*)d_in[3];
    const float* Wq    = (const float*)d_in[4];
    const float* Wk    = (const float*)d_in[5];
    const float* Wv    = (const float*)d_in[6];
    const float* gw    = (const float*)d_in[7];
    const float* gb    = (const float*)d_in[8];
    const float* lng   = (const float*)d_in[9];
    const float* lnb   = (const float*)d_in[10];
    const float* da    = (const float*)d_in[11];
    float* out = (float*)d_out;

    compute_A_kernel<<<DD, DD>>>(Wq, Wk);

    cudaFuncSetAttribute(user_enc_kernel,
                         cudaFuncAttributeMaxDynamicSharedMemorySize, SMEM_BYTES);
    user_enc_kernel<<<BB, NTHREADS, SMEM_BYTES>>>(items, mask, age, pop, Wv,
                                                  gw, gb, lng, lnb, da, out);
}

// round 4
// speedup vs baseline: 2.0100x; 1.4669x over previous
#include <cuda_runtime.h>

#define BB 4096
#define TT 200
#define DD 128
#define KS 5
#define NTHREADS 256

__device__ float g_A[DD * DD];

__global__ void compute_A_kernel(const float* __restrict__ Wq,
                                 const float* __restrict__ Wk) {
    int d = blockIdx.x;
    int e = threadIdx.x;
    float s = 0.f;
#pragma unroll 16
    for (int i = 0; i < DD; ++i)
        s += Wq[i * DD + d] * Wk[i * DD + e];
    g_A[d * DD + e] = s;
}

__device__ __forceinline__ float warp_sum(float v) {
#pragma unroll
    for (int o = 16; o; o >>= 1) v += __shfl_xor_sync(0xffffffffu, v, o);
    return v;
}

__global__ void __launch_bounds__(NTHREADS, 4)
user_enc_kernel(const float* __restrict__ items_g,
                const int* __restrict__ mask_g,
                const float* __restrict__ age_g,
                const float* __restrict__ pop_g,
                const float* __restrict__ Wv,
                const float* __restrict__ gate_w,
                const float* __restrict__ gate_b,
                const float* __restrict__ ln_g,
                const float* __restrict__ ln_b,
                const float* __restrict__ dalpha,
                float* __restrict__ out) {
    __shared__ float s_mask[TT];
    __shared__ float s_age[TT];
    __shared__ float s_pop[TT];
    __shared__ float s_dlog[TT];
    __shared__ float s_mean[DD];
    __shared__ float s_r[DD];
    __shared__ float s_part[1024];   // mean reduce (1024) / r halves (256) / wacc (8*128)
    __shared__ float s_wm[8];
    __shared__ float s_wz[8];
    __shared__ float s_w[DD];
    __shared__ float s_lt[DD];
    __shared__ float s_red[8];
    __shared__ float s_scal[4];

    const int tid  = threadIdx.x;
    const int lane = tid & 31;
    const int warp = tid >> 5;
    const int b    = blockIdx.x;
    const float NEG_INF = __int_as_float(0xff800000);
    const float* row = items_g + (size_t)b * TT * DD;
    const float4* row4 = (const float4*)row;

    // ---- phase 0: metadata + decay-log (parallel) ----
    const float alpha = log1pf(expf(dalpha[0])) + 1e-6f;
    if (tid < TT) {
        int m = mask_g[(size_t)b * TT + tid];
        float a = age_g[(size_t)b * TT + tid];
        s_mask[tid] = m ? 1.f : 0.f;
        s_age[tid]  = a;
        s_pop[tid]  = pop_g[(size_t)b * TT + tid];
        s_dlog[tid] = m ? __logf(__expf(-alpha * a) + 1e-12f) : NEG_INF;
    }
    __syncthreads();

    // ---- pass 1 (DRAM): masked mean accumulation, no staging ----
    {
        float4 acc = make_float4(0.f, 0.f, 0.f, 0.f);
#pragma unroll 5
        for (int k = 0; k < (TT * DD / 4) / NTHREADS; ++k) {  // 25
            int i = tid + k * NTHREADS;
            float4 v = row4[i];
            float m = s_mask[i >> 5];
            acc.x += m * v.x; acc.y += m * v.y; acc.z += m * v.z; acc.w += m * v.w;
        }
        ((float4*)s_part)[tid] = acc;
        if (warp == 0) {
            float c = 0.f;
            for (int t = lane; t < TT; t += 32) c += s_mask[t];
            c = warp_sum(c);
            if (lane == 0) s_scal[0] = c;
        }
    }
    __syncthreads();
    const float cntf = s_scal[0];

    if (tid < DD) {
        int d4 = tid >> 2, comp = tid & 3;
        float s = 0.f;
#pragma unroll
        for (int j = 0; j < 8; ++j)
            s += s_part[(j * 32 + d4) * 4 + comp];
        s_mean[tid] = s / (cntf + 1e-6f);
    }
    __syncthreads();

    // ---- r[e] = sum_d mean[d]*A[d,e], d split over halves ----
    {
        int e = tid & 127, half = tid >> 7;
        const float* Ap = g_A + (size_t)half * 64 * DD + e;
        const float* mp = s_mean + half * 64;
        float r = 0.f;
#pragma unroll 16
        for (int d = 0; d < 64; ++d)
            r += mp[d] * Ap[(size_t)d * DD];
        s_part[half * DD + e] = r;
    }
    __syncthreads();
    if (tid < DD) s_r[tid] = s_part[tid] + s_part[DD + tid];
    __syncthreads();

    // ---- pass 2 (L2): fused scores + online softmax + weighted sum ----
    // warp handles t = warp + 8k, k=0..24. Lane's float4 of x_t reused for
    // both the score dot and the weighted accumulator.
    const float scale = 0.08838834764831845f;  // 1/sqrt(128)
    {
        float4 rv = ((const float4*)s_r)[lane];
        float m = NEG_INF, Z = 0.f;
        float4 acc = make_float4(0.f, 0.f, 0.f, 0.f);
#pragma unroll
        for (int kb = 0; kb < 5; ++kb) {
            float4 xv[5];
            float  dt[5];
#pragma unroll
            for (int j = 0; j < 5; ++j) {
                int t = warp + (kb * 5 + j) * 8;
                xv[j] = row4[t * 32 + lane];
            }
#pragma unroll
            for (int j = 0; j < 5; ++j) {
                float d = xv[j].x * rv.x + xv[j].y * rv.y +
                          xv[j].z * rv.z + xv[j].w * rv.w;
                dt[j] = warp_sum(d);
            }
#pragma unroll
            for (int j = 0; j < 5; ++j) {
                int t = warp + (kb * 5 + j) * 8;
                float dl = s_dlog[t];
                if (dl != NEG_INF) {
                    float s = dt[j] * scale + dl;
                    if (s > m) {
                        float c = __expf(m - s);   // exp(-inf)=0 on first hit
                        Z *= c;
                        acc.x *= c; acc.y *= c; acc.z *= c; acc.w *= c;
                        m = s;
                    }
                    float p = __expf(s - m);
                    Z += p;
                    acc.x += p * xv[j].x; acc.y += p * xv[j].y;
                    acc.z += p * xv[j].z; acc.w += p * xv[j].w;
                }
            }
        }
        // per-warp state -> smem
        ((float4*)s_part)[warp * 32 + lane] = acc;
        if (lane == 0) { s_wm[warp] = m; s_wz[warp] = Z; }
    }
    __syncthreads();

    // ---- merge 8 warps' online-softmax states, w[d] normalized ----
    if (tid < DD) {
        float M = s_wm[0];
#pragma unroll
        for (int j = 1; j < 8; ++j) M = fmaxf(M, s_wm[j]);
        float Zt = 0.f, w = 0.f;
#pragma unroll
        for (int j = 0; j < 8; ++j) {
            float f = __expf(s_wm[j] - M);   // 0 for fully-masked warp
            Zt += f * s_wz[j];
            w  += f * s_part[j * DD + tid];
        }
        s_w[tid] = w / Zt;
    }
    __syncthreads();

    // ---- long_term[e] = sum_d Wv[e,d] * w[d]  (warp-per-e, L2) ----
    {
        float4 wv4 = ((const float4*)s_w)[lane];
#pragma unroll 4
        for (int e = warp; e < DD; e += 8) {
            float4 m4 = ((const float4*)(Wv + (size_t)e * DD))[lane];
            float dot = m4.x * wv4.x + m4.y * wv4.y + m4.z * wv4.z + m4.w * wv4.w;
            dot = warp_sum(dot);
            if (lane == 0) s_lt[e] = dot;
        }
    }
    __syncthreads();

    // ---- short-term window (rows from L2), gate, combine, LayerNorm ----
    float u = 0.f;
    if (tid < DD) {
        int cnt = (int)(cntf + 0.5f);
        if (cnt < 1) cnt = 1;
        int start = cnt - KS;
        if (start < 0) start = 0;
        float dn = (float)(cnt - start);

        float st = 0.f;
        for (int t = start; t < cnt; ++t) st += row[t * DD + tid];
        st /= dn;

        float mp = 0.f, mr = 0.f;
        for (int t = start; t < cnt; ++t) { mp += s_pop[t]; mr += s_age[t]; }
        mp /= dn; mr /= dn;

        float z = mp * gate_w[0] + mr * gate_w[1] + gate_b[0];
        float g = 1.f / (1.f + __expf(-z));
        u = g * st + (1.f - g) * s_lt[tid];
    }

    // ---- block LN over 128 values ----
    {
        float v1 = (tid < DD) ? u : 0.f;
        v1 = warp_sum(v1);
        if (lane == 0) s_red[warp] = v1;
        __syncthreads();
        float mu = (s_red[0] + s_red[1] + s_red[2] + s_red[3]) * (1.f / 128.f);
        __syncthreads();
        float d2 = (tid < DD) ? (u - mu) * (u - mu) : 0.f;
        d2 = warp_sum(d2);
        if (lane == 0) s_red[warp] = d2;
        __syncthreads();
        float var = (s_red[0] + s_red[1] + s_red[2] + s_red[3]) * (1.f / 128.f);
        if (tid < DD) {
            float o = (u - mu) * rsqrtf(var + 1e-5f) * ln_g[tid] + ln_b[tid];
            out[(size_t)b * DD + tid] = o;
        }
    }
}

extern "C" void kernel_launch(void* const* d_in, const int* in_sizes, int n_in,
                              void* d_out, int out_size) {
    const float* items = (const float*)d_in[0];
    const int*   mask  = (const int*)d_in[1];
    const float* age   = (const float*)d_in[2];
    const float* pop   = (const float*)d_in[3];
    const float* Wq    = (const float*)d_in[4];
    const float* Wk    = (const float*)d_in[5];
    const float* Wv    = (const float*)d_in[6];
    const float* gw    = (const float*)d_in[7];
    const float* gb    = (const float*)d_in[8];
    const float* lng   = (const float*)d_in[9];
    const float* lnb   = (const float*)d_in[10];
    const float* da    = (const float*)d_in[11];
    float* out = (float*)d_out;

    compute_A_kernel<<<DD, DD>>>(Wq, Wk);
    user_enc_kernel<<<BB, NTHREADS>>>(items, mask, age, pop, Wv,
                                      gw, gb, lng, lnb, da, out);
}

// round 5
// speedup vs baseline: 2.2750x; 1.1319x over previous
#include <cuda_runtime.h>

#define BB 4096
#define TT 200
#define DD 128
#define KS 5
#define NTHREADS 256

#define CB_ROWS 32
#define WV_S 129
#define CB_SMEM ((DD * WV_S + CB_ROWS * DD) * 4)

__device__ float g_A[DD * DD];
__device__ float g_w[BB * DD];    // normalized attention-weighted sum
__device__ float g_us[BB * DD];   // g * short_term
__device__ float g_omg[BB];       // 1 - g

__global__ void compute_A_kernel(const float* __restrict__ Wq,
                                 const float* __restrict__ Wk) {
    int d = blockIdx.x;
    int e = threadIdx.x;
    float s = 0.f;
#pragma unroll 16
    for (int i = 0; i < DD; ++i)
        s += Wq[i * DD + d] * Wk[i * DD + e];
    g_A[d * DD + e] = s;
}

__device__ __forceinline__ float warp_sum(float v) {
#pragma unroll
    for (int o = 16; o; o >>= 1) v += __shfl_xor_sync(0xffffffffu, v, o);
    return v;
}

__global__ void __launch_bounds__(NTHREADS, 5)
user_enc_kernel(const float* __restrict__ items_g,
                const int* __restrict__ mask_g,
                const float* __restrict__ age_g,
                const float* __restrict__ pop_g,
                const float* __restrict__ gate_w,
                const float* __restrict__ gate_b,
                const float* __restrict__ dalpha) {
    __shared__ float s_mask[TT];
    __shared__ float s_age[TT];
    __shared__ float s_pop[TT];
    __shared__ float s_dlog[TT];
    __shared__ float s_mean[DD];
    __shared__ float s_r[DD];
    __shared__ float s_part[1024];
    __shared__ float s_wm[8];
    __shared__ float s_wz[8];
    __shared__ float s_scal[4];

    const int tid  = threadIdx.x;
    const int lane = tid & 31;
    const int warp = tid >> 5;
    const int b    = blockIdx.x;
    const float NEG_INF = __int_as_float(0xff800000);
    const float* row = items_g + (size_t)b * TT * DD;
    const float4* row4 = (const float4*)row;

    // ---- phase 0: metadata + decay-log (parallel) ----
    const float alpha = log1pf(expf(dalpha[0])) + 1e-6f;
    if (tid < TT) {
        int m = mask_g[(size_t)b * TT + tid];
        float a = age_g[(size_t)b * TT + tid];
        s_mask[tid] = m ? 1.f : 0.f;
        s_age[tid]  = a;
        s_pop[tid]  = pop_g[(size_t)b * TT + tid];
        s_dlog[tid] = m ? __logf(__expf(-alpha * a) + 1e-12f) : NEG_INF;
    }
    __syncthreads();

    // ---- pass 1 (DRAM): masked mean accumulation ----
    {
        float4 acc = make_float4(0.f, 0.f, 0.f, 0.f);
#pragma unroll 5
        for (int k = 0; k < (TT * DD / 4) / NTHREADS; ++k) {  // 25
            int i = tid + k * NTHREADS;
            float4 v = row4[i];
            float m = s_mask[i >> 5];
            acc.x += m * v.x; acc.y += m * v.y; acc.z += m * v.z; acc.w += m * v.w;
        }
        ((float4*)s_part)[tid] = acc;
        if (warp == 0) {
            float c = 0.f;
            for (int t = lane; t < TT; t += 32) c += s_mask[t];
            c = warp_sum(c);
            if (lane == 0) s_scal[0] = c;
        }
    }
    __syncthreads();
    const float cntf = s_scal[0];

    if (tid < DD) {
        int d4 = tid >> 2, comp = tid & 3;
        float s = 0.f;
#pragma unroll
        for (int j = 0; j < 8; ++j)
            s += s_part[(j * 32 + d4) * 4 + comp];
        s_mean[tid] = s / (cntf + 1e-6f);
    }
    __syncthreads();

    // ---- r[e] = sum_d mean[d]*A[d,e], d split over halves ----
    {
        int e = tid & 127, half = tid >> 7;
        const float* Ap = g_A + (size_t)half * 64 * DD + e;
        const float* mp = s_mean + half * 64;
        float r = 0.f;
#pragma unroll 16
        for (int d = 0; d < 64; ++d)
            r += mp[d] * Ap[(size_t)d * DD];
        s_part[half * DD + e] = r;
    }
    __syncthreads();
    if (tid < DD) s_r[tid] = s_part[tid] + s_part[DD + tid];
    __syncthreads();

    // ---- pass 2 (L2): fused scores + online softmax + weighted sum ----
    const float scale = 0.08838834764831845f;  // 1/sqrt(128)
    {
        float4 rv = ((const float4*)s_r)[lane];
        float m = NEG_INF, Z = 0.f;
        float4 acc = make_float4(0.f, 0.f, 0.f, 0.f);
#pragma unroll
        for (int kb = 0; kb < 5; ++kb) {
            float4 xv[5];
            float  dt[5];
#pragma unroll
            for (int j = 0; j < 5; ++j) {
                int t = warp + (kb * 5 + j) * 8;
                xv[j] = row4[t * 32 + lane];
            }
#pragma unroll
            for (int j = 0; j < 5; ++j) {
                float d = xv[j].x * rv.x + xv[j].y * rv.y +
                          xv[j].z * rv.z + xv[j].w * rv.w;
                dt[j] = warp_sum(d);
            }
#pragma unroll
            for (int j = 0; j < 5; ++j) {
                int t = warp + (kb * 5 + j) * 8;
                float dl = s_dlog[t];
                if (dl != NEG_INF) {
                    float s = dt[j] * scale + dl;
                    if (s > m) {
                        float c = __expf(m - s);
                        Z *= c;
                        acc.x *= c; acc.y *= c; acc.z *= c; acc.w *= c;
                        m = s;
                    }
                    float p = __expf(s - m);
                    Z += p;
                    acc.x += p * xv[j].x; acc.y += p * xv[j].y;
                    acc.z += p * xv[j].z; acc.w += p * xv[j].w;
                }
            }
        }
        ((float4*)s_part)[warp * 32 + lane] = acc;
        if (lane == 0) { s_wm[warp] = m; s_wz[warp] = Z; }
    }
    __syncthreads();

    // ---- merge warp states, write normalized w to global scratch ----
    if (tid < DD) {
        float M = s_wm[0];
#pragma unroll
        for (int j = 1; j < 8; ++j) M = fmaxf(M, s_wm[j]);
        float Zt = 0.f, w = 0.f;
#pragma unroll
        for (int j = 0; j < 8; ++j) {
            float f = __expf(s_wm[j] - M);
            Zt += f * s_part[j * DD + tid];   // note: placeholder avoided below
        }
        // recompute properly (separate accumulators)
        Zt = 0.f; w = 0.f;
#pragma unroll
        for (int j = 0; j < 8; ++j) {
            float f = __expf(s_wm[j] - M);
            Zt += f * s_wz[j];
            w  += f * s_part[j * DD + tid];
        }
        g_w[(size_t)b * DD + tid] = w / Zt;
    }

    // ---- short-term window (L2-hot rows), gate; write pre-gated parts ----
    if (tid < DD) {
        int cnt = (int)(cntf + 0.5f);
        if (cnt < 1) cnt = 1;
        int start = cnt - KS;
        if (start < 0) start = 0;
        float dn = (float)(cnt - start);

        float st = 0.f;
        for (int t = start; t < cnt; ++t) st += row[t * DD + tid];
        st /= dn;

        float mp = 0.f, mr = 0.f;
        for (int t = start; t < cnt; ++t) { mp += s_pop[t]; mr += s_age[t]; }
        mp /= dn; mr /= dn;

        float z = mp * gate_w[0] + mr * gate_w[1] + gate_b[0];
        float g = 1.f / (1.f + __expf(-z));
        g_us[(size_t)b * DD + tid] = g * st;
        if (tid == 0) g_omg[b] = 1.f - g;
    }
}

// combine: LT = w @ Wv^T (smem-tiled), user = g_us + (1-g)*LT, LayerNorm, out
__global__ void __launch_bounds__(NTHREADS, 1)
combine_kernel(const float* __restrict__ Wv,
               const float* __restrict__ ln_g,
               const float* __restrict__ ln_b,
               float* __restrict__ out) {
    extern __shared__ float cs[];
    float* wv_s = cs;                 // [DD][WV_S] padded
    float* w_s  = cs + DD * WV_S;     // [CB_ROWS][DD], later reused for LT

    const int tid  = threadIdx.x;
    const int lane = tid & 31;
    const int warp = tid >> 5;
    const int row0 = blockIdx.x * CB_ROWS;

    // load Wv into padded smem (conflict-free reads later)
#pragma unroll
    for (int k = 0; k < 16; ++k) {
        int i = tid + k * NTHREADS;            // float4 index, 4096 total
        float4 f = ((const float4*)Wv)[i];
        int e = i >> 5, d = (i & 31) * 4;
        float* p = wv_s + e * WV_S + d;
        p[0] = f.x; p[1] = f.y; p[2] = f.z; p[3] = f.w;
    }
    // load w rows
#pragma unroll
    for (int k = 0; k < 4; ++k) {
        int i = tid + k * NTHREADS;            // 1024 float4
        ((float4*)w_s)[i] = ((const float4*)(g_w + (size_t)row0 * DD))[i];
    }
    __syncthreads();

    // GEMM: thread tile 4 rows x 4 e (e = lane + 32j -> conflict-free wv_s)
    const int r0 = warp * 4;
    float acc[4][4] = {};
#pragma unroll 4
    for (int d = 0; d < DD; ++d) {
        float wr[4], wv[4];
#pragma unroll
        for (int i = 0; i < 4; ++i) wr[i] = w_s[(r0 + i) * DD + d];
#pragma unroll
        for (int j = 0; j < 4; ++j) wv[j] = wv_s[(lane + 32 * j) * WV_S + d];
#pragma unroll
        for (int i = 0; i < 4; ++i)
#pragma unroll
            for (int j = 0; j < 4; ++j)
                acc[i][j] += wr[i] * wv[j];
    }
    __syncthreads();
    // store LT into w_s (w fully consumed)
#pragma unroll
    for (int i = 0; i < 4; ++i)
#pragma unroll
        for (int j = 0; j < 4; ++j)
            w_s[(r0 + i) * DD + lane + 32 * j] = acc[i][j];
    __syncthreads();

    // LN: warp per row (4 rows per warp)
    const float4 lg4 = ((const float4*)ln_g)[lane];
    const float4 lb4 = ((const float4*)ln_b)[lane];
#pragma unroll
    for (int i = 0; i < 4; ++i) {
        int rr = warp * 4 + i;
        int grow = row0 + rr;
        float4 lt4 = ((const float4*)(w_s + rr * DD))[lane];
        float4 us4 = ((const float4*)(g_us + (size_t)grow * DD))[lane];
        float om = g_omg[grow];
        float4 u;
        u.x = us4.x + om * lt4.x; u.y = us4.y + om * lt4.y;
        u.z = us4.z + om * lt4.z; u.w = us4.w + om * lt4.w;
        float mu = warp_sum(u.x + u.y + u.z + u.w) * (1.f / 128.f);
        float dx = u.x - mu, dy = u.y - mu, dz = u.z - mu, dw = u.w - mu;
        float var = warp_sum(dx * dx + dy * dy + dz * dz + dw * dw) * (1.f / 128.f);
        float rs = rsqrtf(var + 1e-5f);
        float4 o;
        o.x = dx * rs * lg4.x + lb4.x; o.y = dy * rs * lg4.y + lb4.y;
        o.z = dz * rs * lg4.z + lb4.z; o.w = dw * rs * lg4.w + lb4.w;
        ((float4*)(out + (size_t)grow * DD))[lane] = o;
    }
}

extern "C" void kernel_launch(void* const* d_in, const int* in_sizes, int n_in,
                              void* d_out, int out_size) {
    const float* items = (const float*)d_in[0];
    const int*   mask  = (const int*)d_in[1];
    const float* age   = (const float*)d_in[2];
    const float* pop   = (const float*)d_in[3];
    const float* Wq    = (const float*)d_in[4];
    const float* Wk    = (const float*)d_in[5];
    const float* Wv    = (const float*)d_in[6];
    const float* gw    = (const float*)d_in[7];
    const float* gb    = (const float*)d_in[8];
    const float* lng   = (const float*)d_in[9];
    const float* lnb   = (const float*)d_in[10];
    const float* da    = (const float*)d_in[11];
    float* out = (float*)d_out;

    compute_A_kernel<<<DD, DD>>>(Wq, Wk);
    user_enc_kernel<<<BB, NTHREADS>>>(items, mask, age, pop, gw, gb, da);
    cudaFuncSetAttribute(combine_kernel,
                         cudaFuncAttributeMaxDynamicSharedMemorySize, CB_SMEM);
    combine_kernel<<<BB / CB_ROWS, NTHREADS, CB_SMEM>>>(Wv, lng, lnb, out);
}

// round 6
// speedup vs baseline: 2.3259x; 1.0224x over previous
#include <cuda_runtime.h>

#define BB 4096
#define TT 200
#define DD 128
#define KS 5
#define NTHREADS 256

#define CB_ROWS 32
#define WV_S 129
#define CB_SMEM ((DD * WV_S + CB_ROWS * DD) * 4)

__device__ float g_A[DD * DD];
__device__ float g_w[BB * DD];    // normalized attention-weighted sum
__device__ float g_us[BB * DD];   // g * short_term
__device__ float g_omg[BB];       // 1 - g

// A = Wq^T Wk. Each block handles 2 d-columns; Wq columns staged in smem so the
// inner loop is smem-broadcast * coalesced Wk row reads.
__global__ void __launch_bounds__(256, 4)
compute_A_kernel(const float* __restrict__ Wq,
                 const float* __restrict__ Wk) {
    __shared__ float wq0[DD], wq1[DD];
    int tid = threadIdx.x;
    int d0 = blockIdx.x * 2;
    if (tid < DD)           wq0[tid] = Wq[(size_t)tid * DD + d0];
    else                    wq1[tid - DD] = Wq[(size_t)(tid - DD) * DD + d0 + 1];
    __syncthreads();

    int e = tid & 127;
    const float* wq = (tid >> 7) ? wq1 : wq0;
    int d = d0 + (tid >> 7);
    float s = 0.f;
#pragma unroll 16
    for (int i = 0; i < DD; ++i)
        s += wq[i] * Wk[(size_t)i * DD + e];
    g_A[(size_t)d * DD + e] = s;
}

__device__ __forceinline__ float warp_sum(float v) {
#pragma unroll
    for (int o = 16; o; o >>= 1) v += __shfl_xor_sync(0xffffffffu, v, o);
    return v;
}

__global__ void __launch_bounds__(NTHREADS, 5)
user_enc_kernel(const float* __restrict__ items_g,
                const int* __restrict__ mask_g,
                const float* __restrict__ age_g,
                const float* __restrict__ pop_g,
                const float* __restrict__ gate_w,
                const float* __restrict__ gate_b,
                const float* __restrict__ dalpha) {
    __shared__ float s_mask[TT];
    __shared__ float s_age[TT];
    __shared__ float s_pop[TT];
    __shared__ float s_dlog[TT];
    __shared__ float s_mean[DD];
    __shared__ float s_r[DD];
    __shared__ float s_part[1024];
    __shared__ float s_wm[8];
    __shared__ float s_wz[8];
    __shared__ float s_scal[4];

    const int tid  = threadIdx.x;
    const int lane = tid & 31;
    const int warp = tid >> 5;
    const int b    = blockIdx.x;
    const float NEG_INF = __int_as_float(0xff800000);
    const float* row = items_g + (size_t)b * TT * DD;
    const float4* row4 = (const float4*)row;

    // ---- phase 0: metadata + decay-log (parallel) ----
    const float alpha = log1pf(expf(dalpha[0])) + 1e-6f;
    if (tid < TT) {
        int m = mask_g[(size_t)b * TT + tid];
        float a = age_g[(size_t)b * TT + tid];
        s_mask[tid] = m ? 1.f : 0.f;
        s_age[tid]  = a;
        s_pop[tid]  = pop_g[(size_t)b * TT + tid];
        s_dlog[tid] = m ? __logf(__expf(-alpha * a) + 1e-12f) : NEG_INF;
    }
    __syncthreads();

    // ---- pass 1 (DRAM): masked mean accumulation ----
    {
        float4 acc = make_float4(0.f, 0.f, 0.f, 0.f);
#pragma unroll 5
        for (int k = 0; k < (TT * DD / 4) / NTHREADS; ++k) {  // 25
            int i = tid + k * NTHREADS;
            float4 v = row4[i];
            float m = s_mask[i >> 5];
            acc.x += m * v.x; acc.y += m * v.y; acc.z += m * v.z; acc.w += m * v.w;
        }
        ((float4*)s_part)[tid] = acc;
        if (warp == 0) {
            float c = 0.f;
            for (int t = lane; t < TT; t += 32) c += s_mask[t];
            c = warp_sum(c);
            if (lane == 0) s_scal[0] = c;
        }
    }
    __syncthreads();
    const float cntf = s_scal[0];

    if (tid < DD) {
        int d4 = tid >> 2, comp = tid & 3;
        float s = 0.f;
#pragma unroll
        for (int j = 0; j < 8; ++j)
            s += s_part[(j * 32 + d4) * 4 + comp];
        s_mean[tid] = s / (cntf + 1e-6f);
    }
    __syncthreads();

    // ---- r[e] = sum_d mean[d]*A[d,e], d split over halves ----
    {
        int e = tid & 127, half = tid >> 7;
        const float* Ap = g_A + (size_t)half * 64 * DD + e;
        const float* mp = s_mean + half * 64;
        float r = 0.f;
#pragma unroll 16
        for (int d = 0; d < 64; ++d)
            r += mp[d] * Ap[(size_t)d * DD];
        s_part[half * DD + e] = r;
    }
    __syncthreads();
    if (tid < DD) s_r[tid] = s_part[tid] + s_part[DD + tid];
    __syncthreads();

    // ---- pass 2 (L2): fused scores + online softmax + weighted sum ----
    const float scale = 0.08838834764831845f;  // 1/sqrt(128)
    {
        float4 rv = ((const float4*)s_r)[lane];
        float m = NEG_INF, Z = 0.f;
        float4 acc = make_float4(0.f, 0.f, 0.f, 0.f);
#pragma unroll
        for (int kb = 0; kb < 5; ++kb) {
            float4 xv[5];
            float  dt[5];
#pragma unroll
            for (int j = 0; j < 5; ++j) {
                int t = warp + (kb * 5 + j) * 8;
                xv[j] = row4[t * 32 + lane];
            }
#pragma unroll
            for (int j = 0; j < 5; ++j) {
                float d = xv[j].x * rv.x + xv[j].y * rv.y +
                          xv[j].z * rv.z + xv[j].w * rv.w;
                dt[j] = warp_sum(d);
            }
#pragma unroll
            for (int j = 0; j < 5; ++j) {
                int t = warp + (kb * 5 + j) * 8;
                float dl = s_dlog[t];
                if (dl != NEG_INF) {
                    float s = dt[j] * scale + dl;
                    if (s > m) {
                        float c = __expf(m - s);
                        Z *= c;
                        acc.x *= c; acc.y *= c; acc.z *= c; acc.w *= c;
                        m = s;
                    }
                    float p = __expf(s - m);
                    Z += p;
                    acc.x += p * xv[j].x; acc.y += p * xv[j].y;
                    acc.z += p * xv[j].z; acc.w += p * xv[j].w;
                }
            }
        }
        ((float4*)s_part)[warp * 32 + lane] = acc;
        if (lane == 0) { s_wm[warp] = m; s_wz[warp] = Z; }
    }
    __syncthreads();

    // ---- merge warp states, write normalized w to global scratch ----
    if (tid < DD) {
        float M = s_wm[0];
#pragma unroll
        for (int j = 1; j < 8; ++j) M = fmaxf(M, s_wm[j]);
        float Zt = 0.f, w = 0.f;
#pragma unroll
        for (int j = 0; j < 8; ++j) {
            float f = __expf(s_wm[j] - M);
            Zt += f * s_wz[j];
            w  += f * s_part[j * DD + tid];
        }
        g_w[(size_t)b * DD + tid] = w / Zt;
    }

    // ---- short-term window (L2-hot rows), gate; write pre-gated parts ----
    if (tid < DD) {
        int cnt = (int)(cntf + 0.5f);
        if (cnt < 1) cnt = 1;
        int start = cnt - KS;
        if (start < 0) start = 0;
        float dn = (float)(cnt - start);

        float st = 0.f;
        for (int t = start; t < cnt; ++t) st += row[t * DD + tid];
        st /= dn;

        float mp = 0.f, mr = 0.f;
        for (int t = start; t < cnt; ++t) { mp += s_pop[t]; mr += s_age[t]; }
        mp /= dn; mr /= dn;

        float z = mp * gate_w[0] + mr * gate_w[1] + gate_b[0];
        float g = 1.f / (1.f + __expf(-z));
        g_us[(size_t)b * DD + tid] = g * st;
        if (tid == 0) g_omg[b] = 1.f - g;
    }
}

// combine: LT = w @ Wv^T (smem-tiled), user = g_us + (1-g)*LT, LayerNorm, out
__global__ void __launch_bounds__(NTHREADS, 1)
combine_kernel(const float* __restrict__ Wv,
               const float* __restrict__ ln_g,
               const float* __restrict__ ln_b,
               float* __restrict__ out) {
    extern __shared__ float cs[];
    float* wv_s = cs;                 // [DD][WV_S] padded
    float* w_s  = cs + DD * WV_S;     // [CB_ROWS][DD], later reused for LT

    const int tid  = threadIdx.x;
    const int lane = tid & 31;
    const int warp = tid >> 5;
    const int row0 = blockIdx.x * CB_ROWS;

    // load Wv into padded smem (conflict-free reads later)
#pragma unroll
    for (int k = 0; k < 16; ++k) {
        int i = tid + k * NTHREADS;            // float4 index, 4096 total
        float4 f = ((const float4*)Wv)[i];
        int e = i >> 5, d = (i & 31) * 4;
        float* p = wv_s + e * WV_S + d;
        p[0] = f.x; p[1] = f.y; p[2] = f.z; p[3] = f.w;
    }
    // load w rows
#pragma unroll
    for (int k = 0; k < 4; ++k) {
        int i = tid + k * NTHREADS;            // 1024 float4
        ((float4*)w_s)[i] = ((const float4*)(g_w + (size_t)row0 * DD))[i];
    }
    __syncthreads();

    // GEMM: thread tile 4 rows x 4 e (e = lane + 32j -> conflict-free wv_s)
    const int r0 = warp * 4;
    float acc[4][4] = {};
#pragma unroll 4
    for (int d = 0; d < DD; ++d) {
        float wr[4], wv[4];
#pragma unroll
        for (int i = 0; i < 4; ++i) wr[i] = w_s[(r0 + i) * DD + d];
#pragma unroll
        for (int j = 0; j < 4; ++j) wv[j] = wv_s[(lane + 32 * j) * WV_S + d];
#pragma unroll
        for (int i = 0; i < 4; ++i)
#pragma unroll
            for (int j = 0; j < 4; ++j)
                acc[i][j] += wr[i] * wv[j];
    }
    __syncthreads();
    // store LT into w_s (w fully consumed)
#pragma unroll
    for (int i = 0; i < 4; ++i)
#pragma unroll
        for (int j = 0; j < 4; ++j)
            w_s[(r0 + i) * DD + lane + 32 * j] = acc[i][j];
    __syncthreads();

    // LN: warp per row (4 rows per warp)
    const float4 lg4 = ((const float4*)ln_g)[lane];
    const float4 lb4 = ((const float4*)ln_b)[lane];
#pragma unroll
    for (int i = 0; i < 4; ++i) {
        int rr = warp * 4 + i;
        int grow = row0 + rr;
        float4 lt4 = ((const float4*)(w_s + rr * DD))[lane];
        float4 us4 = ((const float4*)(g_us + (size_t)grow * DD))[lane];
        float om = g_omg[grow];
        float4 u;
        u.x = us4.x + om * lt4.x; u.y = us4.y + om * lt4.y;
        u.z = us4.z + om * lt4.z; u.w = us4.w + om * lt4.w;
        float mu = warp_sum(u.x + u.y + u.z + u.w) * (1.f / 128.f);
        float dx = u.x - mu, dy = u.y - mu, dz = u.z - mu, dw = u.w - mu;
        float var = warp_sum(dx * dx + dy * dy + dz * dz + dw * dw) * (1.f / 128.f);
        float rs = rsqrtf(var + 1e-5f);
        float4 o;
        o.x = dx * rs * lg4.x + lb4.x; o.y = dy * rs * lg4.y + lb4.y;
        o.z = dz * rs * lg4.z + lb4.z; o.w = dw * rs * lg4.w + lb4.w;
        ((float4*)(out + (size_t)grow * DD))[lane] = o;
    }
}

extern "C" void kernel_launch(void* const* d_in, const int* in_sizes, int n_in,
                              void* d_out, int out_size) {
    const float* items = (const float*)d_in[0];
    const int*   mask  = (const int*)d_in[1];
    const float* age   = (const float*)d_in[2];
    const float* pop   = (const float*)d_in[3];
    const float* Wq    = (const float*)d_in[4];
    const float* Wk    = (const float*)d_in[5];
    const float* Wv    = (const float*)d_in[6];
    const float* gw    = (const float*)d_in[7];
    const float* gb    = (const float*)d_in[8];
    const float* lng   = (const float*)d_in[9];
    const float* lnb   = (const float*)d_in[10];
    const float* da    = (const float*)d_in[11];
    float* out = (float*)d_out;

    compute_A_kernel<<<DD / 2, 256>>>(Wq, Wk);
    user_enc_kernel<<<BB, NTHREADS>>>(items, mask, age, pop, gw, gb, da);
    cudaFuncSetAttribute(combine_kernel,
                         cudaFuncAttributeMaxDynamicSharedMemorySize, CB_SMEM);
    combine_kernel<<<BB / CB_ROWS, NTHREADS, CB_SMEM>>>(Wv, lng, lnb, out);
}

// round 7
// speedup vs baseline: 2.3726x; 1.0201x over previous
#include <cuda_runtime.h>

#define BB 4096
#define TT 200
#define DD 128
#define KS 5
#define NTHREADS 256

#define STG_T 64                 // tokens staged in smem for pass 2
#define CB_ROWS 32
#define WV_S 129
#define CB_SMEM ((DD * WV_S + CB_ROWS * DD) * 4)

__device__ float g_w[BB * DD];    // normalized attention-weighted sum
__device__ float g_us[BB * DD];   // g * short_term
__device__ float g_omg[BB];       // 1 - g

__device__ __forceinline__ float warp_sum(float v) {
#pragma unroll
    for (int o = 16; o; o >>= 1) v += __shfl_xor_sync(0xffffffffu, v, o);
    return v;
}

__global__ void __launch_bounds__(NTHREADS, 4)
user_enc_kernel(const float* __restrict__ items_g,
                const int* __restrict__ mask_g,
                const float* __restrict__ age_g,
                const float* __restrict__ pop_g,
                const float* __restrict__ Wq,
                const float* __restrict__ Wk,
                const float* __restrict__ gate_w,
                const float* __restrict__ gate_b,
                const float* __restrict__ dalpha) {
    __shared__ float s_stage[STG_T * DD];   // 32 KB: first 64 tokens
    __shared__ float s_mask[TT];
    __shared__ float s_age[TT];
    __shared__ float s_pop[TT];
    __shared__ float s_dlog[TT];
    __shared__ float s_mean[DD];
    __shared__ float s_q[DD];
    __shared__ float s_r[DD];
    __shared__ float s_part[1024];
    __shared__ float s_wm[8];
    __shared__ float s_wz[8];
    __shared__ float s_scal[4];

    const int tid  = threadIdx.x;
    const int lane = tid & 31;
    const int warp = tid >> 5;
    const int b    = blockIdx.x;
    const float NEG_INF = __int_as_float(0xff800000);
    const float* row = items_g + (size_t)b * TT * DD;
    const float4* row4 = (const float4*)row;
    float4* stg4 = (float4*)s_stage;

    // ---- phase 0: metadata + decay-log (parallel) ----
    const float alpha = log1pf(expf(dalpha[0])) + 1e-6f;
    if (tid < TT) {
        int m = mask_g[(size_t)b * TT + tid];
        float a = age_g[(size_t)b * TT + tid];
        s_mask[tid] = m ? 1.f : 0.f;
        s_age[tid]  = a;
        s_pop[tid]  = pop_g[(size_t)b * TT + tid];
        s_dlog[tid] = m ? __logf(__expf(-alpha * a) + 1e-12f) : NEG_INF;
    }
    __syncthreads();

    // ---- pass 1 (DRAM): masked mean accumulation + stage first 64 tokens ----
    {
        float4 acc = make_float4(0.f, 0.f, 0.f, 0.f);
#pragma unroll
        for (int k = 0; k < (TT * DD / 4) / NTHREADS; ++k) {  // 25
            int i = tid + k * NTHREADS;
            float4 v = row4[i];
            if (k < (STG_T * DD / 4) / NTHREADS)   // k<8 -> i<2048 -> t<64
                stg4[i] = v;
            float m = s_mask[i >> 5];
            acc.x += m * v.x; acc.y += m * v.y; acc.z += m * v.z; acc.w += m * v.w;
        }
        ((float4*)s_part)[tid] = acc;
        if (warp == 0) {
            float c = 0.f;
            for (int t = lane; t < TT; t += 32) c += s_mask[t];
            c = warp_sum(c);
            if (lane == 0) s_scal[0] = c;
        }
    }
    __syncthreads();
    const float cntf = s_scal[0];

    if (tid < DD) {
        int d4 = tid >> 2, comp = tid & 3;
        float s = 0.f;
#pragma unroll
        for (int j = 0; j < 8; ++j)
            s += s_part[(j * 32 + d4) * 4 + comp];
        s_mean[tid] = s / (cntf + 1e-6f);
    }
    __syncthreads();

    // ---- q[i] = dot(Wq row i, mean): warp-per-i, coalesced ----
    {
        float4 mv = ((const float4*)s_mean)[lane];
#pragma unroll
        for (int k = 0; k < 16; ++k) {
            int i = warp + k * 8;
            float4 w4 = ((const float4*)(Wq + (size_t)i * DD))[lane];
            float d = w4.x * mv.x + w4.y * mv.y + w4.z * mv.z + w4.w * mv.w;
            d = warp_sum(d);
            if (lane == 0) s_q[i] = d;
        }
    }
    __syncthreads();

    // ---- r[d] = sum_i q[i]*Wk[i,d], i split over halves, coalesced ----
    {
        int e = tid & 127, half = tid >> 7;
        const float* Kp = Wk + (size_t)half * 64 * DD + e;
        const float* qp = s_q + half * 64;
        float r = 0.f;
#pragma unroll 16
        for (int i = 0; i < 64; ++i)
            r += qp[i] * Kp[(size_t)i * DD];
        s_part[half * DD + e] = r;
    }
    __syncthreads();
    if (tid < DD) s_r[tid] = s_part[tid] + s_part[DD + tid];
    __syncthreads();

    // ---- pass 2: fused scores + online softmax + weighted sum ----
    const float scale = 0.08838834764831845f;  // 1/sqrt(128)
    {
        float4 rv = ((const float4*)s_r)[lane];
        float m = NEG_INF, Z = 0.f;
        float4 acc = make_float4(0.f, 0.f, 0.f, 0.f);
#pragma unroll
        for (int kb = 0; kb < 5; ++kb) {
            float4 xv[5];
            float  dt[5];
#pragma unroll
            for (int j = 0; j < 5; ++j) {
                int idx = kb * 5 + j;
                int t = warp + idx * 8;
                xv[j] = (idx < 8) ? stg4[t * 32 + lane] : row4[t * 32 + lane];
            }
#pragma unroll
            for (int j = 0; j < 5; ++j) {
                float d = xv[j].x * rv.x + xv[j].y * rv.y +
                          xv[j].z * rv.z + xv[j].w * rv.w;
                dt[j] = warp_sum(d);
            }
#pragma unroll
            for (int j = 0; j < 5; ++j) {
                int t = warp + (kb * 5 + j) * 8;
                float dl = s_dlog[t];
                if (dl != NEG_INF) {
                    float s = dt[j] * scale + dl;
                    if (s > m) {
                        float c = __expf(m - s);
                        Z *= c;
                        acc.x *= c; acc.y *= c; acc.z *= c; acc.w *= c;
                        m = s;
                    }
                    float p = __expf(s - m);
                    Z += p;
                    acc.x += p * xv[j].x; acc.y += p * xv[j].y;
                    acc.z += p * xv[j].z; acc.w += p * xv[j].w;
                }
            }
        }
        ((float4*)s_part)[warp * 32 + lane] = acc;
        if (lane == 0) { s_wm[warp] = m; s_wz[warp] = Z; }
    }
    __syncthreads();

    // ---- merge warp states, write normalized w to global scratch ----
    if (tid < DD) {
        float M = s_wm[0];
#pragma unroll
        for (int j = 1; j < 8; ++j) M = fmaxf(M, s_wm[j]);
        float Zt = 0.f, w = 0.f;
#pragma unroll
        for (int j = 0; j < 8; ++j) {
            float f = __expf(s_wm[j] - M);
            Zt += f * s_wz[j];
            w  += f * s_part[j * DD + tid];
        }
        g_w[(size_t)b * DD + tid] = w / Zt;
    }

    // ---- short-term window, gate; write pre-gated parts ----
    if (tid < DD) {
        int cnt = (int)(cntf + 0.5f);
        if (cnt < 1) cnt = 1;
        int start = cnt - KS;
        if (start < 0) start = 0;
        float dn = (float)(cnt - start);

        float st = 0.f;
        for (int t = start; t < cnt; ++t)
            st += (cnt <= STG_T) ? s_stage[t * DD + tid] : row[t * DD + tid];
        st /= dn;

        float mp = 0.f, mr = 0.f;
        for (int t = start; t < cnt; ++t) { mp += s_pop[t]; mr += s_age[t]; }
        mp /= dn; mr /= dn;

        float z = mp * gate_w[0] + mr * gate_w[1] + gate_b[0];
        float g = 1.f / (1.f + __expf(-z));
        g_us[(size_t)b * DD + tid] = g * st;
        if (tid == 0) g_omg[b] = 1.f - g;
    }
}

// combine: LT = w @ Wv^T (smem-tiled), user = g_us + (1-g)*LT, LayerNorm, out
__global__ void __launch_bounds__(NTHREADS, 1)
combine_kernel(const float* __restrict__ Wv,
               const float* __restrict__ ln_g,
               const float* __restrict__ ln_b,
               float* __restrict__ out) {
    extern __shared__ float cs[];
    float* wv_s = cs;                 // [DD][WV_S] padded
    float* w_s  = cs + DD * WV_S;     // [CB_ROWS][DD], later reused for LT

    const int tid  = threadIdx.x;
    const int lane = tid & 31;
    const int warp = tid >> 5;
    const int row0 = blockIdx.x * CB_ROWS;

#pragma unroll
    for (int k = 0; k < 16; ++k) {
        int i = tid + k * NTHREADS;
        float4 f = ((const float4*)Wv)[i];
        int e = i >> 5, d = (i & 31) * 4;
        float* p = wv_s + e * WV_S + d;
        p[0] = f.x; p[1] = f.y; p[2] = f.z; p[3] = f.w;
    }
#pragma unroll
    for (int k = 0; k < 4; ++k) {
        int i = tid + k * NTHREADS;
        ((float4*)w_s)[i] = ((const float4*)(g_w + (size_t)row0 * DD))[i];
    }
    __syncthreads();

    const int r0 = warp * 4;
    float acc[4][4] = {};
#pragma unroll 4
    for (int d = 0; d < DD; ++d) {
        float wr[4], wv[4];
#pragma unroll
        for (int i = 0; i < 4; ++i) wr[i] = w_s[(r0 + i) * DD + d];
#pragma unroll
        for (int j = 0; j < 4; ++j) wv[j] = wv_s[(lane + 32 * j) * WV_S + d];
#pragma unroll
        for (int i = 0; i < 4; ++i)
#pragma unroll
            for (int j = 0; j < 4; ++j)
                acc[i][j] += wr[i] * wv[j];
    }
    __syncthreads();
#pragma unroll
    for (int i = 0; i < 4; ++i)
#pragma unroll
        for (int j = 0; j < 4; ++j)
            w_s[(r0 + i) * DD + lane + 32 * j] = acc[i][j];
    __syncthreads();

    const float4 lg4 = ((const float4*)ln_g)[lane];
    const float4 lb4 = ((const float4*)ln_b)[lane];
#pragma unroll
    for (int i = 0; i < 4; ++i) {
        int rr = warp * 4 + i;
        int grow = row0 + rr;
        float4 lt4 = ((const float4*)(w_s + rr * DD))[lane];
        float4 us4 = ((const float4*)(g_us + (size_t)grow * DD))[lane];
        float om = g_omg[grow];
        float4 u;
        u.x = us4.x + om * lt4.x; u.y = us4.y + om * lt4.y;
        u.z = us4.z + om * lt4.z; u.w = us4.w + om * lt4.w;
        float mu = warp_sum(u.x + u.y + u.z + u.w) * (1.f / 128.f);
        float dx = u.x - mu, dy = u.y - mu, dz = u.z - mu, dw = u.w - mu;
        float var = warp_sum(dx * dx + dy * dy + dz * dz + dw * dw) * (1.f / 128.f);
        float rs = rsqrtf(var + 1e-5f);
        float4 o;
        o.x = dx * rs * lg4.x + lb4.x; o.y = dy * rs * lg4.y + lb4.y;
        o.z = dz * rs * lg4.z + lb4.z; o.w = dw * rs * lg4.w + lb4.w;
        ((float4*)(out + (size_t)grow * DD))[lane] = o;
    }
}

extern "C" void kernel_launch(void* const* d_in, const int* in_sizes, int n_in,
                              void* d_out, int out_size) {
    const float* items = (const float*)d_in[0];
    const int*   mask  = (const int*)d_in[1];
    const float* age   = (const float*)d_in[2];
    const float* pop   = (const float*)d_in[3];
    const float* Wq    = (const float*)d_in[4];
    const float* Wk    = (const float*)d_in[5];
    const float* Wv    = (const float*)d_in[6];
    const float* gw    = (const float*)d_in[7];
    const float* gb    = (const float*)d_in[8];
    const float* lng   = (const float*)d_in[9];
    const float* lnb   = (const float*)d_in[10];
    const float* da    = (const float*)d_in[11];
    float* out = (float*)d_out;

    user_enc_kernel<<<BB, NTHREADS>>>(items, mask, age, pop, Wq, Wk, gw, gb, da);
    cudaFuncSetAttribute(combine_kernel,
                         cudaFuncAttributeMaxDynamicSharedMemorySize, CB_SMEM);
    combine_kernel<<<BB / CB_ROWS, NTHREADS, CB_SMEM>>>(Wv, lng, lnb, out);
}